// round 16
// baseline (speedup 1.0000x reference)
#include <cuda_runtime.h>
#include <cuda_bf16.h>
#include <math.h>
#include <stdint.h>

#define CC 4096
#define NN 1024
#define CN (CC*NN)
#define NEGV (-1e30f)

// ---------------- device scratch (no allocations allowed) ----------------
__device__ float d_D0[NN*NN];          // cos0 over compact columns (flag==0)
__device__ float d_D1[NN*NN];          // cos1 over compact columns (flag==1)
__device__ float d_normG[NN];
__device__ float d_normK[NN];
__device__ float d_meanAcc[4];
__device__ int   d_topI[2][NN][2];     // GLOBAL indices
__device__ float d_wfin[8];
__device__ int   d_nc[2];              // compact column counts
__device__ int   d_cpos[2][NN];        // patch -> compact slot (per selection)
__device__ int   d_cmap[2][NN];        // compact slot -> patch
// bf16 2-split operands. A (rows) = G, full. B compacted per z.
__device__ __nv_bfloat16 d_A1[(size_t)NN*CC];
__device__ __nv_bfloat16 d_A2[(size_t)NN*CC];
__device__ __nv_bfloat16 d_B1[2][(size_t)NN*CC];  // [0]=K flag==0, [1]=G flag==1
__device__ __nv_bfloat16 d_B2[2][(size_t)NN*CC];

// ---------------- helpers -------------------------------------------------
__device__ __forceinline__ uint32_t smem_u32(const void* p) {
    uint32_t a;
    asm("{ .reg .u64 t; cvta.to.shared.u64 t, %1; cvt.u32.u64 %0, t; }" : "=r"(a) : "l"(p));
    return a;
}
__device__ __forceinline__ unsigned short bfu(__nv_bfloat16 h) {
    unsigned short u; __builtin_memcpy(&u, &h, 2); return u;
}
__device__ __forceinline__ void cpa16(uint32_t dst, const void* src) {
    asm volatile("cp.async.cg.shared.global [%0], [%1], 16;" :: "r"(dst), "l"(src));
}
__device__ __forceinline__ void ldsm4(uint32_t* r, uint32_t addr) {
    asm volatile("ldmatrix.sync.aligned.m8n8.x4.shared.b16 {%0,%1,%2,%3}, [%4];"
                 : "=r"(r[0]), "=r"(r[1]), "=r"(r[2]), "=r"(r[3]) : "r"(addr));
}
__device__ __forceinline__ void mma16816(float* c, const uint32_t* a, const uint32_t* b) {
    asm volatile("mma.sync.aligned.m16n8k16.row.col.f32.bf16.bf16.f32 "
                 "{%0,%1,%2,%3}, {%4,%5,%6,%7}, {%8,%9}, {%0,%1,%2,%3};"
                 : "+f"(c[0]), "+f"(c[1]), "+f"(c[2]), "+f"(c[3])
                 : "r"(a[0]), "r"(a[1]), "r"(a[2]), "r"(a[3]), "r"(b[0]), "r"(b[1]));
}
__device__ __forceinline__ bool better(float va, int ia, float vb, int ib) {
    return (va > vb) || (va == vb && ia < ib);
}

// ---------------- kernel 0: zero accumulators ----------------------------
__global__ void k_init() {
    int t = blockIdx.x * blockDim.x + threadIdx.x;
    if (t < NN) { d_normG[t] = 0.f; d_normK[t] = 0.f; }
    if (t < 4)  d_meanAcc[t] = 0.f;
}

// ---------------- kernel 0b: flag scan -> compaction tables --------------
__global__ void k_scan(const float* __restrict__ mask) {
    __shared__ int sc[NN];
    int t = threadIdx.x;                  // 1024 threads
    float f = mask[t];
    int sel1 = (f != 0.f) ? 1 : 0;
    int sel0 = 1 - sel1;
    sc[t] = sel0 | (sel1 << 16);
    __syncthreads();
    for (int off = 1; off < NN; off <<= 1) {
        int add = (t >= off) ? sc[t - off] : 0;
        __syncthreads();
        sc[t] += add;
        __syncthreads();
    }
    int inc = sc[t];
    if (sel0) { int p = (inc & 0xffff) - 1; d_cpos[0][t] = p; d_cmap[0][p] = t; }
    else      { int p = (inc >> 16) - 1;    d_cpos[1][t] = p; d_cmap[1][p] = t; }
    if (t == NN - 1) { d_nc[0] = inc & 0xffff; d_nc[1] = inc >> 16; }
}

// ---------------- kernel 1: fused copy + norms + splits (+compaction) ----
__global__ void k_prep(const float* __restrict__ G, const float* __restrict__ Kn,
                       const float* __restrict__ mask, float* __restrict__ out) {
    __shared__ float ts[32][33];
    int z = blockIdx.z;                   // 0 = G, 1 = K
    const float* src = z ? Kn : G;
    float* dst = out + (size_t)z * CN;
    int n0 = blockIdx.x * 32, c0 = blockIdx.y * 32;
    int tx = threadIdx.x, ty = threadIdx.y;          // 32 x 8
    #pragma unroll
    for (int i = 0; i < 4; i++) {
        int cl = ty + i * 8;
        size_t idx = (size_t)(c0 + cl) * NN + n0 + tx;
        float v = src[idx];
        dst[idx] = v;
        ts[cl][tx] = v;
    }
    __syncthreads();
    float* nrm = z ? d_normK : d_normG;
    const int lane16 = tx & 15, hg = tx >> 4;
    const int cpr = lane16 * 2;           // even channel within block
    #pragma unroll
    for (int i = 0; i < 2; i++) {
        int nl = i * 16 + ty * 2 + hg;
        int n  = n0 + nl;
        float v0 = ts[cpr][nl], v1 = ts[cpr + 1][nl];
        float sq = v0 * v0 + v1 * v1;
        #pragma unroll
        for (int off = 8; off; off >>= 1)
            sq += __shfl_down_sync(0xffffffffu, sq, off, 16);
        if (lane16 == 0) atomicAdd(&nrm[n], sq);
        __nv_bfloat16 h10 = __float2bfloat16_rn(v0);
        __nv_bfloat16 h20 = __float2bfloat16_rn(v0 - __bfloat162float(h10));
        __nv_bfloat16 h11 = __float2bfloat16_rn(v1);
        __nv_bfloat16 h21 = __float2bfloat16_rn(v1 - __bfloat162float(h11));
        uint32_t w1 = (uint32_t)bfu(h10) | ((uint32_t)bfu(h11) << 16);
        uint32_t w2 = (uint32_t)bfu(h20) | ((uint32_t)bfu(h21) << 16);
        float fl = mask[n];
        uint32_t ci = (uint32_t)(c0 + cpr) >> 1;   // u32 column index
        if (z == 0) {
            size_t o = (size_t)n * (CC / 2) + ci;
            ((uint32_t*)d_A1)[o] = w1;
            ((uint32_t*)d_A2)[o] = w2;
            if (fl != 0.f) {
                size_t ob = (size_t)d_cpos[1][n] * (CC / 2) + ci;
                ((uint32_t*)d_B1[1])[ob] = w1;
                ((uint32_t*)d_B2[1])[ob] = w2;
            }
        } else {
            if (fl == 0.f) {
                size_t ob = (size_t)d_cpos[0][n] * (CC / 2) + ci;
                ((uint32_t*)d_B1[0])[ob] = w1;
                ((uint32_t*)d_B2[0])[ob] = w2;
            }
        }
    }
}

// ---------------- kernel 2: bf16 mma.sync GEMM, 64x64 tiles --------------
// 256 threads, 8 warps = 2x2 spatial (32x32 warp tiles) x split-K2.
// 3-stage ring (depth-2 prefetch), 109KB smem -> 2 CTAs resident per SM:
// partner CTA's MMA stream covers this CTA's barrier/wait windows.
#define KCHUNK 64
#define NCHK   (CC / KCHUNK)          // 64
#define ROWB   144                    // 128B row + 16B pad
#define TILE1  (64 * ROWB)            // 9216 per operand tile
#define STAGEB (4 * TILE1)            // 36864 (A1,A2,B1,B2)
#define NSTAGE 3
#define SMEM_GEMM (NSTAGE * STAGEB + 1024) // 111616
#define NORMOFF (NSTAGE * STAGEB)
#define REDSTRIDE 34

__global__ __launch_bounds__(256)
void k_gemm_mma() {
    const int z  = blockIdx.z;
    const int nc = d_nc[z];
    const int n0 = blockIdx.x * 64;
    if (n0 >= nc) return;                 // tile fully beyond compact width
    const int m0 = blockIdx.y * 64;

    extern __shared__ char smem[];
    const uint32_t sb = smem_u32(smem);
    const int tid  = threadIdx.x;
    const int lane = tid & 31;
    const int w    = tid >> 5;          // 0..7
    const int ws   = w & 3;             // spatial slot (2 m x 2 n)
    const int kw   = w >> 2;            // k-group
    const int wm   = (ws >> 1) * 32;    // warp m-origin
    const int wn   = (ws & 1) * 32;     // warp n-origin

    const int lrow = tid >> 3;            // 0..31
    const int lc16 = tid & 7;
    const __nv_bfloat16* gA1 = d_A1    + (size_t)(m0 + lrow) * CC + lc16 * 8;
    const __nv_bfloat16* gA2 = d_A2    + (size_t)(m0 + lrow) * CC + lc16 * 8;
    const __nv_bfloat16* gB1 = d_B1[z] + (size_t)(n0 + lrow) * CC + lc16 * 8;
    const __nv_bfloat16* gB2 = d_B2[z] + (size_t)(n0 + lrow) * CC + lc16 * 8;
    const uint32_t sOfs = (uint32_t)(lrow * ROWB + lc16 * 16);

    #define ISSUE(kt, s) do {                                                    \
        uint32_t _d = sb + (uint32_t)(s) * STAGEB + sOfs;                        \
        size_t _ko = (size_t)(kt) * KCHUNK;                                      \
        cpa16(_d,                          gA1 + _ko);                           \
        cpa16(_d + 32 * ROWB,              gA1 + _ko + (size_t)32 * CC);         \
        cpa16(_d + TILE1,                  gA2 + _ko);                           \
        cpa16(_d + TILE1 + 32 * ROWB,      gA2 + _ko + (size_t)32 * CC);         \
        cpa16(_d + 2 * TILE1,              gB1 + _ko);                           \
        cpa16(_d + 2 * TILE1 + 32 * ROWB,  gB1 + _ko + (size_t)32 * CC);         \
        cpa16(_d + 3 * TILE1,              gB2 + _ko);                           \
        cpa16(_d + 3 * TILE1 + 32 * ROWB,  gB2 + _ko + (size_t)32 * CC);         \
    } while (0)

    float acc[2][4][4];
    #pragma unroll
    for (int i = 0; i < 2; i++)
        #pragma unroll
        for (int j = 0; j < 4; j++)
            #pragma unroll
            for (int q = 0; q < 4; q++) acc[i][j][q] = 0.f;

    const uint32_t aOff = (uint32_t)((wm + (lane & 7) + ((lane >> 3) & 1) * 8) * ROWB
                                     + ((lane >> 4) & 1) * 16);
    const uint32_t bOff = (uint32_t)((wn + (lane & 7) + ((lane >> 4) & 1) * 8) * ROWB
                                     + ((lane >> 3) & 1) * 16);

    // prologue: fill 2 of 3 stages
    ISSUE(0, 0); asm volatile("cp.async.commit_group;" ::: "memory");
    ISSUE(1, 1); asm volatile("cp.async.commit_group;" ::: "memory");

    for (int kt = 0; kt < NCHK; kt++) {
        asm volatile("cp.async.wait_group 1;" ::: "memory");  // load kt complete
        __syncthreads();                                       // stage (kt+2)%3 free
        if (kt + 2 < NCHK) ISSUE(kt + 2, (kt + 2) % 3);
        asm volatile("cp.async.commit_group;" ::: "memory");

        const uint32_t stage = sb + (uint32_t)(kt % 3) * STAGEB;
        #pragma unroll
        for (int ksi = 0; ksi < 2; ksi++) {
            const int ks = kw * 2 + ksi;
            uint32_t fa1[8], fa2[8], fb1[8], fb2[8];
            #pragma unroll
            for (int i = 0; i < 2; i++) {
                ldsm4(fa1 + i * 4, stage + aOff + i * (16 * ROWB) + ks * 32);
                ldsm4(fa2 + i * 4, stage + TILE1 + aOff + i * (16 * ROWB) + ks * 32);
            }
            #pragma unroll
            for (int j = 0; j < 2; j++) {
                ldsm4(fb1 + j * 4, stage + 2 * TILE1 + bOff + j * (16 * ROWB) + ks * 32);
                ldsm4(fb2 + j * 4, stage + 3 * TILE1 + bOff + j * (16 * ROWB) + ks * 32);
            }
            #pragma unroll
            for (int i = 0; i < 2; i++)
                #pragma unroll
                for (int j = 0; j < 4; j++)
                    mma16816(acc[i][j], fa1 + i * 4, fb1 + (j >> 1) * 4 + (j & 1) * 2);
            #pragma unroll
            for (int i = 0; i < 2; i++)
                #pragma unroll
                for (int j = 0; j < 4; j++)
                    mma16816(acc[i][j], fa1 + i * 4, fb2 + (j >> 1) * 4 + (j & 1) * 2);
            #pragma unroll
            for (int i = 0; i < 2; i++)
                #pragma unroll
                for (int j = 0; j < 4; j++)
                    mma16816(acc[i][j], fa2 + i * 4, fb1 + (j >> 1) * 4 + (j & 1) * 2);
        }
    }
    asm volatile("cp.async.wait_group 0;" ::: "memory");
    __syncthreads();

    // ---- split-K: kw1 dumps partials; load norms ----
    float* red = (float*)smem;
    float* sNa = (float*)(smem + NORMOFF);
    float* sNb = sNa + 64;
    const int gid = lane >> 2, tig = lane & 3;
    if (kw == 1) {
        float* base = red + ws * (32 * REDSTRIDE);
        #pragma unroll
        for (int i = 0; i < 2; i++)
            #pragma unroll
            for (int half = 0; half < 2; half++) {
                int lr = i * 16 + gid + half * 8;
                float* dst = base + lr * REDSTRIDE;
                #pragma unroll
                for (int j = 0; j < 4; j++) {
                    int lc = j * 8 + tig * 2;
                    *(float2*)&dst[lc] =
                        make_float2(acc[i][j][half * 2], acc[i][j][half * 2 + 1]);
                }
            }
    }
    if (tid < 64) sNa[tid] = d_normG[m0 + tid];
    if (tid >= 64 && tid < 128) {
        int t2 = tid - 64;
        int cc = n0 + t2;
        int g = (cc < nc) ? d_cmap[z][cc] : 0;
        sNb[t2] = (z ? d_normG : d_normK)[g];
    }
    __syncthreads();

    // ---- kw0: sum, cosine, write D (NEGV beyond nc) ----
    if (kw == 0) {
        float* D = z ? d_D1 : d_D0;
        float* base = red + ws * (32 * REDSTRIDE);
        #pragma unroll
        for (int i = 0; i < 2; i++)
            #pragma unroll
            for (int half = 0; half < 2; half++) {
                int lr = i * 16 + gid + half * 8;
                const float* src = base + lr * REDSTRIDE;
                float na = sNa[wm + lr];
                float* Drow = D + (size_t)(m0 + wm + lr) * NN + n0;
                #pragma unroll
                for (int j = 0; j < 4; j++) {
                    int lc = j * 8 + tig * 2;
                    int c = wn + lc;
                    float v0 = acc[i][j][half * 2 + 0] + src[lc];
                    float v1 = acc[i][j][half * 2 + 1] + src[lc + 1];
                    float2 o;
                    o.x = (n0 + c     < nc) ? (v0 / sqrtf(na * sNb[c]))     : NEGV;
                    o.y = (n0 + c + 1 < nc) ? (v1 / sqrtf(na * sNb[c + 1])) : NEGV;
                    *(float2*)&Drow[c] = o;
                }
            }
    }
    #undef ISSUE
}

// ---------------- kernel 3: top-2, one warp per row, shuffle-only --------
__global__ __launch_bounds__(512) void k_topk(const float* __restrict__ flag) {
    int wid  = threadIdx.x >> 5;
    int lane = threadIdx.x & 31;
    int b = blockIdx.x;                   // 128 blocks x 16 warps = 2048 rows
    int z = b >> 6;
    int row = (b & 63) * 16 + wid;
    const float* Dr = (z ? d_D1 : d_D0) + (size_t)row * NN;
    int nc = d_nc[z];
    int width = ((nc + 63) >> 6) << 6;    // written region (64-aligned)

    float v1 = -3.0e38f, v2 = -3.0e38f; int i1 = -1, i2 = -1;
    for (int c = lane * 4; c < width; c += 128) {
        float4 v = *(const float4*)&Dr[c];
        float vv[4] = {v.x, v.y, v.z, v.w};
        #pragma unroll
        for (int j = 0; j < 4; j++) {
            if (better(vv[j], c + j, v1, i1)) { v2 = v1; i2 = i1; v1 = vv[j]; i1 = c + j; }
            else if (better(vv[j], c + j, v2, i2)) { v2 = vv[j]; i2 = c + j; }
        }
    }
    #pragma unroll
    for (int off = 16; off; off >>= 1) {
        float w1 = __shfl_down_sync(0xffffffffu, v1, off);
        int   j1 = __shfl_down_sync(0xffffffffu, i1, off);
        float w2 = __shfl_down_sync(0xffffffffu, v2, off);
        int   j2 = __shfl_down_sync(0xffffffffu, i2, off);
        if (better(v1, i1, w1, j1)) {
            if (!better(v2, i2, w1, j1)) { v2 = w1; i2 = j1; }
        } else {
            if (better(v1, i1, w2, j2)) { v2 = v1; i2 = i1; }
            else                        { v2 = w2; i2 = j2; }
            v1 = w1; i1 = j1;
        }
    }
    if (lane == 0) {
        d_topI[z][row][0] = d_cmap[z][i1];
        d_topI[z][row][1] = d_cmap[z][i2];
        if (flag[row] != 0.f) {
            atomicAdd(&d_meanAcc[z * 2 + 0], v1);
            atomicAdd(&d_meanAcc[z * 2 + 1], v2);
        }
    }
}

// ---------------- kernel 4: softmax weights + row-0 dup artifact ---------
__global__ void k_finalize(const float* __restrict__ flag) {
    __shared__ float sr[256];
    int tid = threadIdx.x;
    float s = 0.f;
    #pragma unroll
    for (int j = 0; j < 4; j++) s += flag[j * 256 + tid];
    sr[tid] = s; __syncthreads();
    for (int st = 128; st > 0; st >>= 1) {
        if (tid < st) sr[tid] += sr[tid + st];
        __syncthreads();
    }
    if (tid == 0) {
        float nm = sr[0];
        float means[4], mx = -3.0e38f;
        for (int i = 0; i < 4; i++) { means[i] = d_meanAcc[i] / nm; mx = fmaxf(mx, means[i]); }
        float e[4], Z = 0.f;
        for (int i = 0; i < 4; i++) { e[i] = expf(means[i] - mx); Z += e[i]; }
        float f0 = flag[0];
        for (int i = 0; i < 4; i++) {
            float w = e[i] / Z;
            int zz = i >> 1, jj = i & 1;
            int col0 = d_topI[zz][0][jj];
            float dup = ((f0 == 1.0f) && (col0 == 0)) ? 0.f : 1.f;
            d_wfin[i] = w;
            d_wfin[4 + i] = w * dup;
        }
    }
}

// ---------------- kernel 5: weighted gather into out[2CN..3CN) -----------
__global__ void k_rtn(const float* __restrict__ G, const float* __restrict__ K,
                      const float* __restrict__ flag, float* __restrict__ out3) {
    __shared__ float w[8];
    int n = threadIdx.x;
    if (n < 8) w[n] = d_wfin[n];
    __syncthreads();
    float fl = flag[n];
    int ia = d_topI[0][n][0], ib = d_topI[0][n][1];
    int ic = d_topI[1][n][0], idd = d_topI[1][n][1];
    int cbase = blockIdx.x * 8;
    #pragma unroll
    for (int cc = 0; cc < 8; cc++) {
        int c = cbase + cc;
        const float* Kr = K + c * NN;
        const float* Gr = G + c * NN;
        float v = 0.f;
        if (fl == 1.0f)
            v = w[0] * Kr[ia] + w[1] * Kr[ib] + w[2] * Gr[ic] + w[3] * Gr[idd];
        if (n == 0)
            v += w[4] * Kr[0] + w[5] * Kr[0] + w[6] * Gr[0] + w[7] * Gr[0];
        out3[c * NN + n] = v;
    }
}

// ---------------- launch --------------------------------------------------
extern "C" void kernel_launch(void* const* d_in, const int* in_sizes, int n_in,
                              void* d_out, int out_size) {
    (void)in_sizes; (void)n_in; (void)out_size;
    const float* G = (const float*)d_in[0];   // generated (1,4096,32,32)
    const float* K = (const float*)d_in[1];   // known
    const float* M = (const float*)d_in[2];   // mask -> flag[1024]
    float* out = (float*)d_out;

    cudaFuncSetAttribute(k_gemm_mma, cudaFuncAttributeMaxDynamicSharedMemorySize, SMEM_GEMM);

    k_init<<<4, 256>>>();
    k_scan<<<1, 1024>>>(M);
    k_prep<<<dim3(32, 128, 2), dim3(32, 8)>>>(G, K, M, out);
    k_gemm_mma<<<dim3(16, 16, 2), 256, SMEM_GEMM>>>();
    k_topk<<<128, 512>>>(M);
    k_finalize<<<1, 256>>>(M);
    k_rtn<<<512, 1024>>>(G, K, M, out + (size_t)2 * CN);
}

// round 17
// speedup vs baseline: 1.0398x; 1.0398x over previous
#include <cuda_runtime.h>
#include <cuda_bf16.h>
#include <math.h>
#include <stdint.h>

#define CC 4096
#define NN 1024
#define CN (CC*NN)
#define NEGV (-1e30f)

// ---------------- device scratch (no allocations allowed) ----------------
__device__ float d_D0[NN*NN];          // cos0 over compact columns (flag==0)
__device__ float d_D1[NN*NN];          // cos1 over compact columns (flag==1)
__device__ float d_normG[NN];
__device__ float d_normK[NN];
__device__ float d_meanAcc[4];
__device__ int   d_topI[2][NN][2];     // GLOBAL indices
__device__ int   d_nc[2];              // compact column counts (nc[1] == nm)
__device__ int   d_cpos[2][NN];        // patch -> compact slot (per selection)
__device__ int   d_cmap[2][NN];        // compact slot -> patch
// bf16 2-split operands. A (rows) = G, full. B compacted per z.
__device__ __nv_bfloat16 d_A1[(size_t)NN*CC];
__device__ __nv_bfloat16 d_A2[(size_t)NN*CC];
__device__ __nv_bfloat16 d_B1[2][(size_t)NN*CC];  // [0]=K flag==0, [1]=G flag==1
__device__ __nv_bfloat16 d_B2[2][(size_t)NN*CC];

// ---------------- helpers -------------------------------------------------
__device__ __forceinline__ uint32_t smem_u32(const void* p) {
    uint32_t a;
    asm("{ .reg .u64 t; cvta.to.shared.u64 t, %1; cvt.u32.u64 %0, t; }" : "=r"(a) : "l"(p));
    return a;
}
__device__ __forceinline__ unsigned short bfu(__nv_bfloat16 h) {
    unsigned short u; __builtin_memcpy(&u, &h, 2); return u;
}
__device__ __forceinline__ void cpa16(uint32_t dst, const void* src) {
    asm volatile("cp.async.cg.shared.global [%0], [%1], 16;" :: "r"(dst), "l"(src));
}
__device__ __forceinline__ void ldsm4(uint32_t* r, uint32_t addr) {
    asm volatile("ldmatrix.sync.aligned.m8n8.x4.shared.b16 {%0,%1,%2,%3}, [%4];"
                 : "=r"(r[0]), "=r"(r[1]), "=r"(r[2]), "=r"(r[3]) : "r"(addr));
}
__device__ __forceinline__ void mma16816(float* c, const uint32_t* a, const uint32_t* b) {
    asm volatile("mma.sync.aligned.m16n8k16.row.col.f32.bf16.bf16.f32 "
                 "{%0,%1,%2,%3}, {%4,%5,%6,%7}, {%8,%9}, {%0,%1,%2,%3};"
                 : "+f"(c[0]), "+f"(c[1]), "+f"(c[2]), "+f"(c[3])
                 : "r"(a[0]), "r"(a[1]), "r"(a[2]), "r"(a[3]), "r"(b[0]), "r"(b[1]));
}
__device__ __forceinline__ bool better(float va, int ia, float vb, int ib) {
    return (va > vb) || (va == vb && ia < ib);
}

// ---------------- kernel 0: flag scan + zero accumulators ----------------
__global__ void k_scan(const float* __restrict__ mask) {
    __shared__ int sc[NN];
    int t = threadIdx.x;                  // 1024 threads
    d_normG[t] = 0.f; d_normK[t] = 0.f;
    if (t < 4) d_meanAcc[t] = 0.f;
    float f = mask[t];
    int sel1 = (f != 0.f) ? 1 : 0;
    int sel0 = 1 - sel1;
    sc[t] = sel0 | (sel1 << 16);
    __syncthreads();
    for (int off = 1; off < NN; off <<= 1) {
        int add = (t >= off) ? sc[t - off] : 0;
        __syncthreads();
        sc[t] += add;
        __syncthreads();
    }
    int inc = sc[t];
    if (sel0) { int p = (inc & 0xffff) - 1; d_cpos[0][t] = p; d_cmap[0][p] = t; }
    else      { int p = (inc >> 16) - 1;    d_cpos[1][t] = p; d_cmap[1][p] = t; }
    if (t == NN - 1) { d_nc[0] = inc & 0xffff; d_nc[1] = inc >> 16; }
}

// ---------------- kernel 1: fused copy + norms + splits (+compaction) ----
// 32x8 threads. Write phase: 16-lane groups handle 2 adjacent channels,
// packed u32 stores into the bf16 split arrays.
__global__ void k_prep(const float* __restrict__ G, const float* __restrict__ Kn,
                       const float* __restrict__ mask, float* __restrict__ out) {
    __shared__ float ts[32][33];
    int z = blockIdx.z;                   // 0 = G, 1 = K
    const float* src = z ? Kn : G;
    float* dst = out + (size_t)z * CN;
    int n0 = blockIdx.x * 32, c0 = blockIdx.y * 32;
    int tx = threadIdx.x, ty = threadIdx.y;          // 32 x 8
    #pragma unroll
    for (int i = 0; i < 4; i++) {
        int cl = ty + i * 8;
        size_t idx = (size_t)(c0 + cl) * NN + n0 + tx;
        float v = src[idx];
        dst[idx] = v;
        ts[cl][tx] = v;
    }
    __syncthreads();
    float* nrm = z ? d_normK : d_normG;
    const int lane16 = tx & 15, hg = tx >> 4;
    const int cpr = lane16 * 2;           // even channel within block
    #pragma unroll
    for (int i = 0; i < 2; i++) {
        int nl = i * 16 + ty * 2 + hg;
        int n  = n0 + nl;
        float v0 = ts[cpr][nl], v1 = ts[cpr + 1][nl];
        float sq = v0 * v0 + v1 * v1;
        #pragma unroll
        for (int off = 8; off; off >>= 1)
            sq += __shfl_down_sync(0xffffffffu, sq, off, 16);
        if (lane16 == 0) atomicAdd(&nrm[n], sq);
        __nv_bfloat16 h10 = __float2bfloat16_rn(v0);
        __nv_bfloat16 h20 = __float2bfloat16_rn(v0 - __bfloat162float(h10));
        __nv_bfloat16 h11 = __float2bfloat16_rn(v1);
        __nv_bfloat16 h21 = __float2bfloat16_rn(v1 - __bfloat162float(h11));
        uint32_t w1 = (uint32_t)bfu(h10) | ((uint32_t)bfu(h11) << 16);
        uint32_t w2 = (uint32_t)bfu(h20) | ((uint32_t)bfu(h21) << 16);
        float fl = mask[n];
        uint32_t ci = (uint32_t)(c0 + cpr) >> 1;   // u32 column index
        if (z == 0) {
            size_t o = (size_t)n * (CC / 2) + ci;
            ((uint32_t*)d_A1)[o] = w1;
            ((uint32_t*)d_A2)[o] = w2;
            if (fl != 0.f) {
                size_t ob = (size_t)d_cpos[1][n] * (CC / 2) + ci;
                ((uint32_t*)d_B1[1])[ob] = w1;
                ((uint32_t*)d_B2[1])[ob] = w2;
            }
        } else {
            if (fl == 0.f) {
                size_t ob = (size_t)d_cpos[0][n] * (CC / 2) + ci;
                ((uint32_t*)d_B1[0])[ob] = w1;
                ((uint32_t*)d_B2[0])[ob] = w2;
            }
        }
    }
}

// ---------------- kernel 2: bf16 mma.sync GEMM, 128x64 tiles -------------
// 512 threads, 16 warps = 4x2 spatial (32x32 warp tiles) x split-K2.
// 4-stage ring, depth-3 prefetch, one barrier/chunk. (Best-measured R14 cfg;
// mma.sync duty wall ~45% is the HW roofline for this path on sm_103a.)
#define KCHUNK 64
#define NCHK   (CC / KCHUNK)          // 64
#define ROWB   144                    // 128B row + 16B pad
#define ATILE  (128 * ROWB)           // 18432
#define BTILE  (64 * ROWB)            // 9216
#define STAGEB (2 * ATILE + 2 * BTILE)// 55296
#define NSTAGE 4
#define SMEM_GEMM (NSTAGE * STAGEB + 1024) // 222208
#define NORMOFF (NSTAGE * STAGEB)
#define REDSTRIDE 34

__global__ __launch_bounds__(512)
void k_gemm_mma() {
    const int z  = blockIdx.z;
    const int nc = d_nc[z];
    const int n0 = blockIdx.x * 64;
    if (n0 >= nc) return;                 // tile fully beyond compact width
    const int m0 = blockIdx.y * 128;

    extern __shared__ char smem[];
    const uint32_t sb = smem_u32(smem);
    const int tid  = threadIdx.x;
    const int lane = tid & 31;
    const int w    = tid >> 5;          // 0..15
    const int ws   = w & 7;             // spatial slot (4 m x 2 n)
    const int kw   = w >> 3;            // k-group
    const int wm   = (ws >> 1) * 32;    // warp m-origin
    const int wn   = (ws & 1) * 32;     // warp n-origin

    const int lrow = tid >> 3;            // 0..63
    const int lc16 = tid & 7;
    const __nv_bfloat16* gA1 = d_A1    + (size_t)(m0 + lrow) * CC + lc16 * 8;
    const __nv_bfloat16* gA2 = d_A2    + (size_t)(m0 + lrow) * CC + lc16 * 8;
    const __nv_bfloat16* gB1 = d_B1[z] + (size_t)(n0 + lrow) * CC + lc16 * 8;
    const __nv_bfloat16* gB2 = d_B2[z] + (size_t)(n0 + lrow) * CC + lc16 * 8;
    const uint32_t sOfs = (uint32_t)(lrow * ROWB + lc16 * 16);

    #define ISSUE(kt, s) do {                                                    \
        uint32_t _d = sb + (uint32_t)(s) * STAGEB + sOfs;                        \
        size_t _ko = (size_t)(kt) * KCHUNK;                                      \
        cpa16(_d,                          gA1 + _ko);                           \
        cpa16(_d + 64 * ROWB,              gA1 + _ko + (size_t)64 * CC);         \
        cpa16(_d + ATILE,                  gA2 + _ko);                           \
        cpa16(_d + ATILE + 64 * ROWB,      gA2 + _ko + (size_t)64 * CC);         \
        cpa16(_d + 2 * ATILE,              gB1 + _ko);                           \
        cpa16(_d + 2 * ATILE + BTILE,      gB2 + _ko);                           \
    } while (0)

    float acc[2][4][4];
    #pragma unroll
    for (int i = 0; i < 2; i++)
        #pragma unroll
        for (int j = 0; j < 4; j++)
            #pragma unroll
            for (int q = 0; q < 4; q++) acc[i][j][q] = 0.f;

    const uint32_t aOff = (uint32_t)((wm + (lane & 7) + ((lane >> 3) & 1) * 8) * ROWB
                                     + ((lane >> 4) & 1) * 16);
    const uint32_t bOff = (uint32_t)((wn + (lane & 7) + ((lane >> 4) & 1) * 8) * ROWB
                                     + ((lane >> 3) & 1) * 16);

    // prologue: fill 3 of 4 stages
    ISSUE(0, 0); asm volatile("cp.async.commit_group;" ::: "memory");
    ISSUE(1, 1); asm volatile("cp.async.commit_group;" ::: "memory");
    ISSUE(2, 2); asm volatile("cp.async.commit_group;" ::: "memory");

    for (int kt = 0; kt < NCHK; kt++) {
        asm volatile("cp.async.wait_group 2;" ::: "memory");  // load kt complete
        __syncthreads();                                       // stage (kt+3)&3 free
        if (kt + 3 < NCHK) ISSUE(kt + 3, (kt + 3) & 3);
        asm volatile("cp.async.commit_group;" ::: "memory");

        const uint32_t stage = sb + (uint32_t)(kt & 3) * STAGEB;
        uint32_t fa1[2][8], fa2[2][8], fb1[2][8], fb2[2][8];
        #pragma unroll
        for (int ksi = 0; ksi < 2; ksi++) {
            const int ks = kw * 2 + ksi;
            #pragma unroll
            for (int i = 0; i < 2; i++) {
                ldsm4(fa1[ksi] + i * 4, stage + aOff + i * (16 * ROWB) + ks * 32);
                ldsm4(fa2[ksi] + i * 4, stage + ATILE + aOff + i * (16 * ROWB) + ks * 32);
            }
            #pragma unroll
            for (int j = 0; j < 2; j++) {
                ldsm4(fb1[ksi] + j * 4, stage + 2 * ATILE + bOff + j * (16 * ROWB) + ks * 32);
                ldsm4(fb2[ksi] + j * 4, stage + 2 * ATILE + BTILE + bOff + j * (16 * ROWB) + ks * 32);
            }
        }
        #pragma unroll
        for (int ksi = 0; ksi < 2; ksi++)
            #pragma unroll
            for (int i = 0; i < 2; i++)
                #pragma unroll
                for (int j = 0; j < 4; j++) {
                    mma16816(acc[i][j], fa1[ksi] + i * 4, fb1[ksi] + j * 2);
                    mma16816(acc[i][j], fa1[ksi] + i * 4, fb2[ksi] + j * 2);
                    mma16816(acc[i][j], fa2[ksi] + i * 4, fb1[ksi] + j * 2);
                }
    }
    asm volatile("cp.async.wait_group 0;" ::: "memory");
    __syncthreads();

    // ---- split-K: kw1 dumps partials; load norms ----
    float* red = (float*)smem;
    float* sNa = (float*)(smem + NORMOFF);
    float* sNb = sNa + 128;
    const int gid = lane >> 2, tig = lane & 3;
    if (kw == 1) {
        float* base = red + ws * (32 * REDSTRIDE);
        #pragma unroll
        for (int i = 0; i < 2; i++)
            #pragma unroll
            for (int half = 0; half < 2; half++) {
                int lr = i * 16 + gid + half * 8;
                float* dst = base + lr * REDSTRIDE;
                #pragma unroll
                for (int j = 0; j < 4; j++) {
                    int lc = j * 8 + tig * 2;
                    *(float2*)&dst[lc] =
                        make_float2(acc[i][j][half * 2], acc[i][j][half * 2 + 1]);
                }
            }
    }
    if (tid < 128) sNa[tid] = d_normG[m0 + tid];
    if (tid >= 128 && tid < 192) {
        int t2 = tid - 128;
        int cc = n0 + t2;
        int g = (cc < nc) ? d_cmap[z][cc] : 0;
        sNb[t2] = (z ? d_normG : d_normK)[g];
    }
    __syncthreads();

    // ---- kw0: sum, cosine, write D (NEGV beyond nc) ----
    if (kw == 0) {
        float* D = z ? d_D1 : d_D0;
        float* base = red + ws * (32 * REDSTRIDE);
        #pragma unroll
        for (int i = 0; i < 2; i++)
            #pragma unroll
            for (int half = 0; half < 2; half++) {
                int lr = i * 16 + gid + half * 8;
                const float* src = base + lr * REDSTRIDE;
                float na = sNa[wm + lr];
                float* Drow = D + (size_t)(m0 + wm + lr) * NN + n0;
                #pragma unroll
                for (int j = 0; j < 4; j++) {
                    int lc = j * 8 + tig * 2;
                    int c = wn + lc;
                    float v0 = acc[i][j][half * 2 + 0] + src[lc];
                    float v1 = acc[i][j][half * 2 + 1] + src[lc + 1];
                    float2 o;
                    o.x = (n0 + c     < nc) ? (v0 / sqrtf(na * sNb[c]))     : NEGV;
                    o.y = (n0 + c + 1 < nc) ? (v1 / sqrtf(na * sNb[c + 1])) : NEGV;
                    *(float2*)&Drow[c] = o;
                }
            }
    }
    #undef ISSUE
}

// ---------------- kernel 3: top-2, one warp per row, shuffle-only --------
__global__ __launch_bounds__(512) void k_topk(const float* __restrict__ flag) {
    int wid  = threadIdx.x >> 5;
    int lane = threadIdx.x & 31;
    int b = blockIdx.x;                   // 128 blocks x 16 warps = 2048 rows
    int z = b >> 6;
    int row = (b & 63) * 16 + wid;
    const float* Dr = (z ? d_D1 : d_D0) + (size_t)row * NN;
    int nc = d_nc[z];
    int width = ((nc + 63) >> 6) << 6;    // written region (64-aligned)

    float v1 = -3.0e38f, v2 = -3.0e38f; int i1 = -1, i2 = -1;
    for (int c = lane * 4; c < width; c += 128) {
        float4 v = *(const float4*)&Dr[c];
        float vv[4] = {v.x, v.y, v.z, v.w};
        #pragma unroll
        for (int j = 0; j < 4; j++) {
            if (better(vv[j], c + j, v1, i1)) { v2 = v1; i2 = i1; v1 = vv[j]; i1 = c + j; }
            else if (better(vv[j], c + j, v2, i2)) { v2 = vv[j]; i2 = c + j; }
        }
    }
    #pragma unroll
    for (int off = 16; off; off >>= 1) {
        float w1 = __shfl_down_sync(0xffffffffu, v1, off);
        int   j1 = __shfl_down_sync(0xffffffffu, i1, off);
        float w2 = __shfl_down_sync(0xffffffffu, v2, off);
        int   j2 = __shfl_down_sync(0xffffffffu, i2, off);
        if (better(v1, i1, w1, j1)) {
            if (!better(v2, i2, w1, j1)) { v2 = w1; i2 = j1; }
        } else {
            if (better(v1, i1, w2, j2)) { v2 = v1; i2 = i1; }
            else                        { v2 = w2; i2 = j2; }
            v1 = w1; i1 = j1;
        }
    }
    if (lane == 0) {
        d_topI[z][row][0] = d_cmap[z][i1];
        d_topI[z][row][1] = d_cmap[z][i2];
        if (flag[row] != 0.f) {
            atomicAdd(&d_meanAcc[z * 2 + 0], v1);
            atomicAdd(&d_meanAcc[z * 2 + 1], v2);
        }
    }
}

// ---------------- kernel 4: weighted gather (computes weights inline) ----
__global__ void k_rtn(const float* __restrict__ G, const float* __restrict__ K,
                      const float* __restrict__ flag, float* __restrict__ out3) {
    __shared__ float w[8];
    int n = threadIdx.x;
    if (n == 0) {
        float nm = (float)d_nc[1];         // count of flag!=0
        float means[4], mx = -3.0e38f;
        #pragma unroll
        for (int i = 0; i < 4; i++) { means[i] = d_meanAcc[i] / nm; mx = fmaxf(mx, means[i]); }
        float e[4], Z = 0.f;
        #pragma unroll
        for (int i = 0; i < 4; i++) { e[i] = expf(means[i] - mx); Z += e[i]; }
        float f0 = flag[0];
        #pragma unroll
        for (int i = 0; i < 4; i++) {
            float wv = e[i] / Z;
            int zz = i >> 1, jj = i & 1;
            int col0 = d_topI[zz][0][jj];
            float dup = ((f0 == 1.0f) && (col0 == 0)) ? 0.f : 1.f;
            w[i] = wv;
            w[4 + i] = wv * dup;
        }
    }
    __syncthreads();
    float fl = flag[n];
    int ia = d_topI[0][n][0], ib = d_topI[0][n][1];
    int ic = d_topI[1][n][0], idd = d_topI[1][n][1];
    int cbase = blockIdx.x * 8;
    #pragma unroll
    for (int cc = 0; cc < 8; cc++) {
        int c = cbase + cc;
        const float* Kr = K + c * NN;
        const float* Gr = G + c * NN;
        float v = 0.f;
        if (fl == 1.0f)
            v = w[0] * Kr[ia] + w[1] * Kr[ib] + w[2] * Gr[ic] + w[3] * Gr[idd];
        if (n == 0)
            v += w[4] * Kr[0] + w[5] * Kr[0] + w[6] * Gr[0] + w[7] * Gr[0];
        out3[c * NN + n] = v;
    }
}

// ---------------- launch --------------------------------------------------
extern "C" void kernel_launch(void* const* d_in, const int* in_sizes, int n_in,
                              void* d_out, int out_size) {
    (void)in_sizes; (void)n_in; (void)out_size;
    const float* G = (const float*)d_in[0];   // generated (1,4096,32,32)
    const float* K = (const float*)d_in[1];   // known
    const float* M = (const float*)d_in[2];   // mask -> flag[1024]
    float* out = (float*)d_out;

    cudaFuncSetAttribute(k_gemm_mma, cudaFuncAttributeMaxDynamicSharedMemorySize, SMEM_GEMM);

    k_scan<<<1, 1024>>>(M);
    k_prep<<<dim3(32, 128, 2), dim3(32, 8)>>>(G, K, M, out);
    k_gemm_mma<<<dim3(16, 8, 2), 512, SMEM_GEMM>>>();
    k_topk<<<128, 512>>>(M);
    k_rtn<<<512, 1024>>>(G, K, M, out + (size_t)2 * CN);
}